// round 14
// baseline (speedup 1.0000x reference)
#include <cuda_runtime.h>
#include <cuda_bf16.h>
#include <cstdint>
#include <math.h>

// ============================================================
// DocAttention via Gram-matrix restructure (sm_103 family-safe mma.sync).
//   M = Wq @ Wk^T ;  S_b = cls_b @ M @ cls_b^T
//   logits[b,x] = sum_{a!=x, m_a=1} S_b[x,a] (+ exact bias terms via u,v,c0)
//   out = softmax(logits + (1-m)*-1e5)
// K1: converts (cls, W) + u,v,c0 GEMVs     (pure streaming, no transpose)
// K2: MT[e][d] = sum_h Wk[e,h] Wq[d,h]     (both operands native layout!)
// K3: per (batch-pair, e-slice): P = cls@M slice, S-MMA, last-CTA softmax
// ============================================================

__device__ __forceinline__ uint32_t smem_u32(const void* p) {
    uint32_t a;
    asm("{ .reg .u64 t; cvta.to.shared.u64 t, %1; cvt.u32.u64 %0, t; }"
        : "=r"(a) : "l"(p));
    return a;
}

// ---------------- scratch ----------------
__device__ __align__(16) __nv_bfloat16 g_A[1024 * 1024];      // cls bf16 [row][d]
__device__ __align__(16) __nv_bfloat16 g_Wbf[2 * 1024 * 1024];// Wq | Wk bf16 native [d][h]
__device__ __align__(16) __nv_bfloat16 g_MT[1024 * 1024];     // MT[e][d] bf16
__device__ float g_u[1024];
__device__ float g_v[1024];
__device__ float g_c0;
__device__ float g_part[32 * 8 * 1024];                        // [b][slice][32*32]
__device__ int   g_bctr[32];

// ================= K1: converts + GEMVs =================
// blocks [0,128): cls (8 rows/blk, warp per row)
// blocks [128,384): W elementwise stream
// blocks [384,392): u = Wq @ bk     [392,400): v = Wk @ bq    400: c0
__global__ __launch_bounds__(256) void k1_convert(const float* __restrict__ enc,
                                                  const float* __restrict__ wq,
                                                  const float* __restrict__ wk,
                                                  const float* __restrict__ bq,
                                                  const float* __restrict__ bk) {
    const int blk = blockIdx.x;
    const int tid = threadIdx.x, warp = tid >> 5, lane = tid & 31;

    if (blk < 128) {
        const int row = blk * 8 + warp;
        const float4* __restrict__ src =
            reinterpret_cast<const float4*>(enc + (size_t)row * 131072);
        uint2* __restrict__ dst = reinterpret_cast<uint2*>(g_A + (size_t)row * 1024);
        float4 v[8];
        #pragma unroll
        for (int i = 0; i < 8; i++) v[i] = src[lane + 32 * i];
        #pragma unroll
        for (int i = 0; i < 8; i++) {
            __nv_bfloat16 h[4];
            h[0] = __float2bfloat16(v[i].x);
            h[1] = __float2bfloat16(v[i].y);
            h[2] = __float2bfloat16(v[i].z);
            h[3] = __float2bfloat16(v[i].w);
            dst[lane + 32 * i] = *reinterpret_cast<uint2*>(h);
        }
        return;
    }
    if (blk < 384) {
        const int idx = blk - 128;           // 0..255, each 8192 floats
        const float* __restrict__ src =
            (idx < 128) ? (wq + (size_t)idx * 8192) : (wk + (size_t)(idx - 128) * 8192);
        const float4* __restrict__ s4 = reinterpret_cast<const float4*>(src);
        uint2* __restrict__ d2 = reinterpret_cast<uint2*>(g_Wbf + (size_t)idx * 8192);
        #pragma unroll
        for (int i = 0; i < 8; i++) {
            const float4 v = s4[tid + 256 * i];
            __nv_bfloat16 h[4];
            h[0] = __float2bfloat16(v.x);
            h[1] = __float2bfloat16(v.y);
            h[2] = __float2bfloat16(v.z);
            h[3] = __float2bfloat16(v.w);
            d2[tid + 256 * i] = *reinterpret_cast<uint2*>(h);
        }
        return;
    }
    if (blk < 400) {
        const bool isU = (blk < 392);
        const float* __restrict__ W = isU ? wq : wk;
        const float* __restrict__ bvec = isU ? bk : bq;
        float* __restrict__ dst = isU ? g_u : g_v;
        const int d0 = (blk - (isU ? 384 : 392)) * 128;
        #pragma unroll
        for (int di = 0; di < 16; di++) {
            const int d = d0 + warp * 16 + di;
            float acc = 0.f;
            #pragma unroll
            for (int j = 0; j < 32; j++) {
                const int h = lane + j * 32;
                acc = fmaf(W[(size_t)d * 1024 + h], bvec[h], acc);
            }
            #pragma unroll
            for (int o = 16; o > 0; o >>= 1)
                acc += __shfl_xor_sync(0xFFFFFFFFu, acc, o);
            if (lane == 0) dst[d] = acc;
        }
        return;
    }
    if (warp == 0) {
        float acc = 0.f;
        #pragma unroll
        for (int j = 0; j < 32; j++) {
            const int h = lane + j * 32;
            acc = fmaf(bq[h], bk[h], acc);
        }
        #pragma unroll
        for (int o = 16; o > 0; o >>= 1)
            acc += __shfl_xor_sync(0xFFFFFFFFu, acc, o);
        if (lane == 0) g_c0 = acc;
    }
}

// ================= K2: MT GEMM =================
// MT[e][d], tiles 128e x 64d per CTA; grid (16 dt, 8 et) = 128 CTAs.
// A = Wk rows e (native), B = Wq rows d (native). Warp tile 32x32.
#define BK 64
#define STG 24576           // (128 + 64) rows * 128 B
#define NST 4

__global__ __launch_bounds__(256, 1)
void k2_mt_gemm() {
    extern __shared__ __align__(1024) char smem[];
    const uint32_t base = smem_u32(smem);
    const int tid = threadIdx.x, warp = tid >> 5, lane = tid & 31;
    const int dBase = blockIdx.x * 64;
    const int eBase = blockIdx.y * 128;
    const int mw = (warp & 3) * 32;      // e within tile
    const int nw = (warp >> 2) * 32;     // d within tile
    const int lj = lane >> 3, li = lane & 7;

    float c[2][4][4];
    #pragma unroll
    for (int i = 0; i < 2; i++)
        #pragma unroll
        for (int j = 0; j < 4; j++)
            #pragma unroll
            for (int r = 0; r < 4; r++) c[i][j][r] = 0.f;

    const __nv_bfloat16* __restrict__ Wk_ = g_Wbf + 1048576;
    const __nv_bfloat16* __restrict__ Wq_ = g_Wbf;

    auto issue = [&](int kb) {
        const int stage = kb & (NST - 1);
        const uint32_t sA = base + (uint32_t)stage * STG;
        const uint32_t sB = sA + 16384;
        const int k0 = kb * BK;
        #pragma unroll
        for (int i = 0; i < 4; i++) {       // A: 128 rows x 8 ch
            const int idx = i * 256 + tid;
            const int row = idx >> 3, ch = idx & 7;
            const __nv_bfloat16* g = Wk_ + (size_t)(eBase + row) * 1024 + k0 + ch * 8;
            asm volatile("cp.async.cg.shared.global [%0], [%1], 16;"
                :: "r"(sA + (uint32_t)(row * 128 + ((ch ^ (row & 7)) << 4))), "l"(g));
        }
        #pragma unroll
        for (int i = 0; i < 2; i++) {       // B: 64 rows x 8 ch
            const int idx = i * 256 + tid;
            const int row = idx >> 3, ch = idx & 7;
            const __nv_bfloat16* g = Wq_ + (size_t)(dBase + row) * 1024 + k0 + ch * 8;
            asm volatile("cp.async.cg.shared.global [%0], [%1], 16;"
                :: "r"(sB + (uint32_t)(row * 128 + ((ch ^ (row & 7)) << 4))), "l"(g));
        }
        asm volatile("cp.async.commit_group;");
    };

    auto compute = [&](int stage) {
        const uint32_t sA = base + (uint32_t)stage * STG;
        const uint32_t sB = sA + 16384;
        #pragma unroll
        for (int kc = 0; kc < 4; kc++) {
            uint32_t a[2][4];
            #pragma unroll
            for (int mt = 0; mt < 2; mt++) {
                const int row = mw + mt * 16 + ((lj & 1) << 3) + li;
                const int ch = kc * 2 + (lj >> 1);
                asm volatile("ldmatrix.sync.aligned.m8n8.x4.shared.b16 "
                             "{%0,%1,%2,%3}, [%4];"
                             : "=r"(a[mt][0]), "=r"(a[mt][1]),
                               "=r"(a[mt][2]), "=r"(a[mt][3])
                             : "r"(sA + (uint32_t)(row * 128 + ((ch ^ (row & 7)) << 4))));
            }
            uint32_t b[2][4];
            #pragma unroll
            for (int nh = 0; nh < 2; nh++) {
                const int row = nw + nh * 16 + ((lj >> 1) << 3) + li;
                const int ch = kc * 2 + (lj & 1);
                asm volatile("ldmatrix.sync.aligned.m8n8.x4.shared.b16 "
                             "{%0,%1,%2,%3}, [%4];"
                             : "=r"(b[nh][0]), "=r"(b[nh][1]),
                               "=r"(b[nh][2]), "=r"(b[nh][3])
                             : "r"(sB + (uint32_t)(row * 128 + ((ch ^ (row & 7)) << 4))));
            }
            #pragma unroll
            for (int mt = 0; mt < 2; mt++)
                #pragma unroll
                for (int nt = 0; nt < 4; nt++) {
                    asm volatile(
                        "mma.sync.aligned.m16n8k16.row.col.f32.bf16.bf16.f32 "
                        "{%0,%1,%2,%3}, {%4,%5,%6,%7}, {%8,%9}, {%0,%1,%2,%3};"
                        : "+f"(c[mt][nt][0]), "+f"(c[mt][nt][1]),
                          "+f"(c[mt][nt][2]), "+f"(c[mt][nt][3])
                        : "r"(a[mt][0]), "r"(a[mt][1]), "r"(a[mt][2]), "r"(a[mt][3]),
                          "r"(b[nt >> 1][(nt & 1) * 2]),
                          "r"(b[nt >> 1][(nt & 1) * 2 + 1]));
                }
        }
    };

    issue(0); issue(1); issue(2);
    for (int kb = 0; kb < 16; kb++) {
        if (kb < 14)       asm volatile("cp.async.wait_group 2;");
        else if (kb == 14) asm volatile("cp.async.wait_group 1;");
        else               asm volatile("cp.async.wait_group 0;");
        __syncthreads();
        if (kb + 3 < 16) issue(kb + 3);
        compute(kb & (NST - 1));
    }

    #pragma unroll
    for (int mt = 0; mt < 2; mt++)
        #pragma unroll
        for (int half = 0; half < 2; half++) {
            const int e = eBase + mw + mt * 16 + (lane >> 2) + half * 8;
            #pragma unroll
            for (int nt = 0; nt < 4; nt++) {
                const int d = dBase + nw + nt * 8 + (lane & 3) * 2;
                __nv_bfloat162 hv;
                hv.x = __float2bfloat16(c[mt][nt][half * 2 + 0]);
                hv.y = __float2bfloat16(c[mt][nt][half * 2 + 1]);
                *reinterpret_cast<__nv_bfloat162*>(&g_MT[(size_t)e * 1024 + d]) = hv;
            }
        }
}

// ================= K3: fused P = cls@M, S-MMA, softmax =================
// grid (8 slices, 16 pairs). CTA: rows = batches (2p,2p+1) = 64 cls rows,
// cols = e-slice of 128. smem: 4 stages x 24KB + cls 16KB = 112KB.
#define K3_SMEM (4 * STG + 16384)

__global__ __launch_bounds__(256, 1)
void k3_fused(const int* __restrict__ mask, float* __restrict__ out) {
    extern __shared__ __align__(1024) char smem[];
    const uint32_t base = smem_u32(smem);
    const int tid = threadIdx.x, warp = tid >> 5, lane = tid & 31;
    const int slice = blockIdx.x;        // e-slice of 128
    const int p = blockIdx.y;            // batch pair
    const int n0e = slice * 128;
    const int mw = (warp & 1) * 32;      // cls row within 64
    const int nw = (warp >> 1) * 32;     // e-local within 128
    const int lj = lane >> 3, li = lane & 7;
    const uint32_t clsB = base + 4 * STG;   // cls slice region

    // cls slice for S stage: 64 rows x 16 ch, same swizzle as P
    #pragma unroll
    for (int i = 0; i < 4; i++) {
        const int idx = i * 256 + tid;
        const int row = idx >> 4, ch = idx & 15;
        const int swz = (ch & 8) | ((ch ^ (row & 7)) & 7);
        const __nv_bfloat16* g = g_A + (size_t)(p * 64 + row) * 1024 + n0e + ch * 8;
        asm volatile("cp.async.cg.shared.global [%0], [%1], 16;"
                     :: "r"(clsB + (uint32_t)(row * 256 + swz * 16)), "l"(g));
    }
    asm volatile("cp.async.commit_group;");

    float c[2][4][4];
    #pragma unroll
    for (int i = 0; i < 2; i++)
        #pragma unroll
        for (int j = 0; j < 4; j++)
            #pragma unroll
            for (int r = 0; r < 4; r++) c[i][j][r] = 0.f;

    auto issue = [&](int kb) {
        const int stage = kb & (NST - 1);
        const uint32_t sA = base + (uint32_t)stage * STG;
        const uint32_t sB = sA + 8192;
        const int k0 = kb * BK;
        #pragma unroll
        for (int i = 0; i < 2; i++) {    // A: cls 64 rows x 8 ch
            const int idx = i * 256 + tid;
            const int row = idx >> 3, ch = idx & 7;
            const __nv_bfloat16* g = g_A + (size_t)(p * 64 + row) * 1024 + k0 + ch * 8;
            asm volatile("cp.async.cg.shared.global [%0], [%1], 16;"
                :: "r"(sA + (uint32_t)(row * 128 + ((ch ^ (row & 7)) << 4))), "l"(g));
        }
        #pragma unroll
        for (int i = 0; i < 4; i++) {    // B: MT 128 e-rows x 8 ch
            const int idx = i * 256 + tid;
            const int row = idx >> 3, ch = idx & 7;
            const __nv_bfloat16* g = g_MT + (size_t)(n0e + row) * 1024 + k0 + ch * 8;
            asm volatile("cp.async.cg.shared.global [%0], [%1], 16;"
                :: "r"(sB + (uint32_t)(row * 128 + ((ch ^ (row & 7)) << 4))), "l"(g));
        }
        asm volatile("cp.async.commit_group;");
    };

    auto compute = [&](int stage) {
        const uint32_t sA = base + (uint32_t)stage * STG;
        const uint32_t sB = sA + 8192;
        #pragma unroll
        for (int kc = 0; kc < 4; kc++) {
            uint32_t a[2][4];
            #pragma unroll
            for (int mt = 0; mt < 2; mt++) {
                const int row = mw + mt * 16 + ((lj & 1) << 3) + li;
                const int ch = kc * 2 + (lj >> 1);
                asm volatile("ldmatrix.sync.aligned.m8n8.x4.shared.b16 "
                             "{%0,%1,%2,%3}, [%4];"
                             : "=r"(a[mt][0]), "=r"(a[mt][1]),
                               "=r"(a[mt][2]), "=r"(a[mt][3])
                             : "r"(sA + (uint32_t)(row * 128 + ((ch ^ (row & 7)) << 4))));
            }
            uint32_t b[2][4];
            #pragma unroll
            for (int nh = 0; nh < 2; nh++) {
                const int row = nw + nh * 16 + ((lj >> 1) << 3) + li;
                const int ch = kc * 2 + (lj & 1);
                asm volatile("ldmatrix.sync.aligned.m8n8.x4.shared.b16 "
                             "{%0,%1,%2,%3}, [%4];"
                             : "=r"(b[nh][0]), "=r"(b[nh][1]),
                               "=r"(b[nh][2]), "=r"(b[nh][3])
                             : "r"(sB + (uint32_t)(row * 128 + ((ch ^ (row & 7)) << 4))));
            }
            #pragma unroll
            for (int mt = 0; mt < 2; mt++)
                #pragma unroll
                for (int nt = 0; nt < 4; nt++) {
                    asm volatile(
                        "mma.sync.aligned.m16n8k16.row.col.f32.bf16.bf16.f32 "
                        "{%0,%1,%2,%3}, {%4,%5,%6,%7}, {%8,%9}, {%0,%1,%2,%3};"
                        : "+f"(c[mt][nt][0]), "+f"(c[mt][nt][1]),
                          "+f"(c[mt][nt][2]), "+f"(c[mt][nt][3])
                        : "r"(a[mt][0]), "r"(a[mt][1]), "r"(a[mt][2]), "r"(a[mt][3]),
                          "r"(b[nt >> 1][(nt & 1) * 2]), "r"(b[nt >> 1][(nt & 1) * 2 + 1]));
                }
        }
    };

    issue(0); issue(1); issue(2);
    for (int kb = 0; kb < 16; kb++) {
        if (kb < 14)       asm volatile("cp.async.wait_group 2;");
        else if (kb == 14) asm volatile("cp.async.wait_group 1;");
        else               asm volatile("cp.async.wait_group 0;");
        __syncthreads();
        if (kb + 3 < 16) issue(kb + 3);
        compute(kb & (NST - 1));
    }
    __syncthreads();

    // ---- store P (bf16) into [0,16KB): 64 rows x 256 B, swizzled ----
    #pragma unroll
    for (int mt = 0; mt < 2; mt++)
        #pragma unroll
        for (int half = 0; half < 2; half++) {
            const int x = mw + mt * 16 + (lane >> 2) + half * 8;
            #pragma unroll
            for (int nt = 0; nt < 4; nt++) {
                const int eloc = nw + nt * 8 + (lane & 3) * 2;
                const int ch = eloc >> 3;
                const int swz = (ch & 8) | ((ch ^ (x & 7)) & 7);
                __nv_bfloat162 hv;
                hv.x = __float2bfloat16(c[mt][nt][half * 2 + 0]);
                hv.y = __float2bfloat16(c[mt][nt][half * 2 + 1]);
                *reinterpret_cast<__nv_bfloat162*>(
                    smem + x * 256 + swz * 16 + (lane & 3) * 4) = hv;
            }
        }
    __syncthreads();

    // ---- S-MMA: warp w handles kc = w (16 e-cols) ----
    float cs[2][2][4][4];    // [batch][mt-local][nt-local][4]
    #pragma unroll
    for (int bi = 0; bi < 2; bi++)
        #pragma unroll
        for (int i = 0; i < 2; i++)
            #pragma unroll
            for (int j = 0; j < 4; j++)
                #pragma unroll
                for (int r = 0; r < 4; r++) cs[bi][i][j][r] = 0.f;
    {
        uint32_t as[4][4], bs[4][4];
        #pragma unroll
        for (int mt = 0; mt < 4; mt++) {
            const int row = mt * 16 + ((lj & 1) << 3) + li;
            const int ch = warp * 2 + (lj >> 1);
            const int swz = (ch & 8) | ((ch ^ (row & 7)) & 7);
            asm volatile("ldmatrix.sync.aligned.m8n8.x4.shared.b16 "
                         "{%0,%1,%2,%3}, [%4];"
                         : "=r"(as[mt][0]), "=r"(as[mt][1]),
                           "=r"(as[mt][2]), "=r"(as[mt][3])
                         : "r"(base + (uint32_t)(row * 256 + swz * 16)));
        }
        #pragma unroll
        for (int nh = 0; nh < 4; nh++) {
            const int row = nh * 16 + ((lj >> 1) << 3) + li;
            const int ch = warp * 2 + (lj & 1);
            const int swz = (ch & 8) | ((ch ^ (row & 7)) & 7);
            asm volatile("ldmatrix.sync.aligned.m8n8.x4.shared.b16 "
                         "{%0,%1,%2,%3}, [%4];"
                         : "=r"(bs[nh][0]), "=r"(bs[nh][1]),
                           "=r"(bs[nh][2]), "=r"(bs[nh][3])
                         : "r"(clsB + (uint32_t)(row * 256 + swz * 16)));
        }
        #pragma unroll
        for (int bi = 0; bi < 2; bi++)
            #pragma unroll
            for (int mtl = 0; mtl < 2; mtl++) {
                const int mt = bi * 2 + mtl;
                #pragma unroll
                for (int ntl = 0; ntl < 4; ntl++) {
                    const int ng = bi * 4 + ntl;
                    asm volatile(
                        "mma.sync.aligned.m16n8k16.row.col.f32.bf16.bf16.f32 "
                        "{%0,%1,%2,%3}, {%4,%5,%6,%7}, {%8,%9}, {%0,%1,%2,%3};"
                        : "+f"(cs[bi][mtl][ntl][0]), "+f"(cs[bi][mtl][ntl][1]),
                          "+f"(cs[bi][mtl][ntl][2]), "+f"(cs[bi][mtl][ntl][3])
                        : "r"(as[mt][0]), "r"(as[mt][1]), "r"(as[mt][2]), "r"(as[mt][3]),
                          "r"(bs[ng >> 1][(ng & 1) * 2]), "r"(bs[ng >> 1][(ng & 1) * 2 + 1]));
                }
            }
    }
    // store per-warp partial S to S8 at [16KB, 80KB)
    float* __restrict__ S8 = reinterpret_cast<float*>(smem + 16384);
    #pragma unroll
    for (int bi = 0; bi < 2; bi++)
        #pragma unroll
        for (int mtl = 0; mtl < 2; mtl++)
            #pragma unroll
            for (int half = 0; half < 2; half++) {
                const int xl = mtl * 16 + (lane >> 2) + half * 8;
                #pragma unroll
                for (int ntl = 0; ntl < 4; ntl++) {
                    const int y = ntl * 8 + (lane & 3) * 2;
                    float2 v;
                    v.x = cs[bi][mtl][ntl][half * 2 + 0];
                    v.y = cs[bi][mtl][ntl][half * 2 + 1];
                    *reinterpret_cast<float2*>(
                        &S8[(warp * 2 + bi) * 1024 + xl * 32 + y]) = v;
                }
            }
    __syncthreads();

    // reduce 8 warps -> g_part
    #pragma unroll
    for (int t = 0; t < 8; t++) {
        const int idx = tid + t * 256;       // 0..2047
        const int bi = idx >> 10, e = idx & 1023;
        float s = 0.f;
        #pragma unroll
        for (int w8 = 0; w8 < 8; w8++) s += S8[(w8 * 2 + bi) * 1024 + e];
        g_part[(size_t)(p * 2 + bi) * 8192 + slice * 1024 + e] = s;
    }

    // ---- per-batch completion counters ----
    __shared__ int lastF[2];
    __syncthreads();
    if (tid == 0) {
        __threadfence();
        lastF[0] = (atomicAdd(&g_bctr[p * 2 + 0], 1) == 7);
        lastF[1] = (atomicAdd(&g_bctr[p * 2 + 1], 1) == 7);
    }
    __syncthreads();

    __shared__ float Sf[1024];
    __shared__ float mrow[32], tv[32], rv[32], lg[32], scal[2];
    #pragma unroll
    for (int bi = 0; bi < 2; bi++) {
        if (!lastF[bi]) continue;
        const int b = p * 2 + bi;
        if (tid == 0) __threadfence();
        __syncthreads();
        #pragma unroll
        for (int t = 0; t < 4; t++) {
            const int idx = tid + t * 256;
            float s = 0.f;
            #pragma unroll
            for (int sl = 0; sl < 8; sl++)
                s += g_part[(size_t)b * 8192 + sl * 1024 + idx];
            Sf[idx] = s;
        }
        if (tid < 32) mrow[tid] = (float)mask[b * 32 + tid];
        __syncthreads();
        // t_x = cls_x . u ; r_x = cls_x . v
        #pragma unroll
        for (int xi = 0; xi < 4; xi++) {
            const int x = warp * 4 + xi;
            const __nv_bfloat16* __restrict__ crow = g_A + (size_t)(b * 32 + x) * 1024;
            float ta = 0.f, ra = 0.f;
            #pragma unroll
            for (int j = 0; j < 32; j++) {
                const int d = lane + j * 32;
                const float cv = __bfloat162float(crow[d]);
                ta = fmaf(cv, g_u[d], ta);
                ra = fmaf(cv, g_v[d], ra);
            }
            #pragma unroll
            for (int o = 16; o > 0; o >>= 1) {
                ta += __shfl_xor_sync(0xFFFFFFFFu, ta, o);
                ra += __shfl_xor_sync(0xFFFFFFFFu, ra, o);
            }
            if (lane == 0) { tv[x] = ta; rv[x] = ra; }
        }
        __syncthreads();
        if (warp == 0) {
            float R = mrow[lane] * rv[lane];
            float cA = mrow[lane];
            #pragma unroll
            for (int o = 16; o > 0; o >>= 1) {
                R += __shfl_xor_sync(0xFFFFFFFFu, R, o);
                cA += __shfl_xor_sync(0xFFFFFFFFu, cA, o);
            }
            if (lane == 0) { scal[0] = R; scal[1] = cA; }
        }
        __syncthreads();
        const float R = scal[0], cA = scal[1], c0 = g_c0;
        #pragma unroll
        for (int xi = 0; xi < 4; xi++) {
            const int x = warp * 4 + xi;
            float s = mrow[lane] * Sf[x * 32 + lane];
            #pragma unroll
            for (int o = 16; o > 0; o >>= 1)
                s += __shfl_xor_sync(0xFFFFFFFFu, s, o);
            if (lane == 0)
                lg[x] = (mrow[x] != 0.f)
                    ? (s - Sf[x * 33] + tv[x] * (cA - 1.f) + (R - rv[x]) + c0 * (cA - 1.f))
                    : -100000.0f;
        }
        __syncthreads();
        if (warp == 0) {
            float v = lg[lane];
            float mx = v;
            #pragma unroll
            for (int o = 16; o > 0; o >>= 1)
                mx = fmaxf(mx, __shfl_xor_sync(0xFFFFFFFFu, mx, o));
            const float e = expf(v - mx);
            float sum = e;
            #pragma unroll
            for (int o = 16; o > 0; o >>= 1)
                sum += __shfl_xor_sync(0xFFFFFFFFu, sum, o);
            out[b * 32 + lane] = e / sum;
        }
        if (tid == 0) g_bctr[b] = 0;
        __syncthreads();
    }
}

extern "C" void kernel_launch(void* const* d_in, const int* in_sizes, int n_in,
                              void* d_out, int out_size) {
    const float* enc  = (const float*)d_in[0];
    const int*   mask = (const int*)  d_in[1];
    const float* wq   = (const float*)d_in[2];
    const float* bq   = (const float*)d_in[3];
    const float* wk   = (const float*)d_in[4];
    const float* bk   = (const float*)d_in[5];
    float* out = (float*)d_out;

    cudaFuncSetAttribute(k2_mt_gemm, cudaFuncAttributeMaxDynamicSharedMemorySize,
                         NST * STG);
    cudaFuncSetAttribute(k3_fused, cudaFuncAttributeMaxDynamicSharedMemorySize,
                         K3_SMEM);

    k1_convert<<<401, 256>>>(enc, wq, wk, bq, bk);
    k2_mt_gemm<<<dim3(16, 8), 256, NST * STG>>>();
    k3_fused<<<dim3(8, 16), 256, K3_SMEM>>>(mask, out);
}

// round 15
// speedup vs baseline: 1.7588x; 1.7588x over previous
#include <cuda_runtime.h>
#include <cuda_bf16.h>
#include <cstdint>
#include <math.h>

// ============================================================
// DocAttention via Gram-matrix restructure (sm_103 family-safe mma.sync).
//   M = Wq @ Wk^T ;  S_b = cls_b @ M @ cls_b^T
//   logits[b,x] = sum_{a!=x, m_a=1} S_b[x,a] (+ exact bias terms via u,v,c0)
//   out = softmax(logits + (1-m)*-1e5)
// K1: converts (cls, W) with u,v GEMVs FUSED into the W stream + c0
// K2: MT[e][d] = sum_h Wk[e,h] Wq[d,h]   (128x128 tiles, R4 datapath)
// K3: per (batch-pair, e-slice): P = cls@M slice, S-MMA, last-CTA softmax
// ============================================================

__device__ __forceinline__ uint32_t smem_u32(const void* p) {
    uint32_t a;
    asm("{ .reg .u64 t; cvta.to.shared.u64 t, %1; cvt.u32.u64 %0, t; }"
        : "=r"(a) : "l"(p));
    return a;
}

// ---------------- scratch ----------------
__device__ __align__(16) __nv_bfloat16 g_A[1024 * 1024];      // cls bf16 [row][d]
__device__ __align__(16) __nv_bfloat16 g_Wbf[2 * 1024 * 1024];// Wq | Wk bf16 native [d][h]
__device__ __align__(16) __nv_bfloat16 g_MT[1024 * 1024];     // MT[e][d] bf16
__device__ float g_u[1024];
__device__ float g_v[1024];
__device__ float g_c0;
__device__ float g_part[32 * 8 * 1024];                        // [b][slice][32*32]
__device__ int   g_bctr[32];

// ================= K1: converts + fused GEMVs =================
// blocks [0,128): cls (8 rows/blk, warp per row)
// blocks [128,384): W stream (8 d-rows each) + fused u/v dot vs bias vec
// block 384: c0 = bq . bk
__global__ __launch_bounds__(256) void k1_convert(const float* __restrict__ enc,
                                                  const float* __restrict__ wq,
                                                  const float* __restrict__ wk,
                                                  const float* __restrict__ bq,
                                                  const float* __restrict__ bk) {
    const int blk = blockIdx.x;
    const int tid = threadIdx.x, warp = tid >> 5, lane = tid & 31;

    if (blk < 128) {
        const int row = blk * 8 + warp;
        const float4* __restrict__ src =
            reinterpret_cast<const float4*>(enc + (size_t)row * 131072);
        uint2* __restrict__ dst = reinterpret_cast<uint2*>(g_A + (size_t)row * 1024);
        float4 v[8];
        #pragma unroll
        for (int i = 0; i < 8; i++) v[i] = src[lane + 32 * i];
        #pragma unroll
        for (int i = 0; i < 8; i++) {
            __nv_bfloat16 h[4];
            h[0] = __float2bfloat16(v[i].x);
            h[1] = __float2bfloat16(v[i].y);
            h[2] = __float2bfloat16(v[i].z);
            h[3] = __float2bfloat16(v[i].w);
            dst[lane + 32 * i] = *reinterpret_cast<uint2*>(h);
        }
        return;
    }
    if (blk < 384) {
        __shared__ float red[64];            // [warp][row]
        const int idx = blk - 128;           // 0..255, 8 rows of 1024 each
        const bool isU = (idx < 128);
        const int rowbase = (isU ? idx : idx - 128) * 8;
        const float* __restrict__ src =
            isU ? (wq + (size_t)idx * 8192) : (wk + (size_t)(idx - 128) * 8192);
        const float* __restrict__ bvec = isU ? bk : bq;
        float* __restrict__ dstv = isU ? g_u : g_v;

        const float4* __restrict__ s4 = reinterpret_cast<const float4*>(src);
        uint2* __restrict__ d2 = reinterpret_cast<uint2*>(g_Wbf + (size_t)idx * 8192);
        float4 v[8];
        #pragma unroll
        for (int i = 0; i < 8; i++) v[i] = s4[tid + 256 * i];
        #pragma unroll
        for (int i = 0; i < 8; i++) {
            __nv_bfloat16 h[4];
            h[0] = __float2bfloat16(v[i].x);
            h[1] = __float2bfloat16(v[i].y);
            h[2] = __float2bfloat16(v[i].z);
            h[3] = __float2bfloat16(v[i].w);
            d2[tid + 256 * i] = *reinterpret_cast<uint2*>(h);
        }
        // fused GEMV: v[i] is row (rowbase+i), cols tid*4..tid*4+4
        const float4 bv = reinterpret_cast<const float4*>(bvec)[tid];
        float p[8];
        #pragma unroll
        for (int i = 0; i < 8; i++) {
            p[i] = v[i].x * bv.x;
            p[i] = fmaf(v[i].y, bv.y, p[i]);
            p[i] = fmaf(v[i].z, bv.z, p[i]);
            p[i] = fmaf(v[i].w, bv.w, p[i]);
        }
        #pragma unroll
        for (int i = 0; i < 8; i++)
            #pragma unroll
            for (int o = 16; o > 0; o >>= 1)
                p[i] += __shfl_xor_sync(0xFFFFFFFFu, p[i], o);
        if (lane == 0)
            #pragma unroll
            for (int i = 0; i < 8; i++) red[warp * 8 + i] = p[i];
        __syncthreads();
        if (tid < 8) {
            float s = 0.f;
            #pragma unroll
            for (int w = 0; w < 8; w++) s += red[w * 8 + tid];
            dstv[rowbase + tid] = s;
        }
        return;
    }
    if (warp == 0) {
        float acc = 0.f;
        #pragma unroll
        for (int j = 0; j < 32; j++) {
            const int h = lane + j * 32;
            acc = fmaf(bq[h], bk[h], acc);
        }
        #pragma unroll
        for (int o = 16; o > 0; o >>= 1)
            acc += __shfl_xor_sync(0xFFFFFFFFu, acc, o);
        if (lane == 0) g_c0 = acc;
    }
}

// ================= K2: MT GEMM (128x128 tiles, R4 datapath) =================
// MT[e][d]; grid (8 dt, 8 et) = 64 CTAs. A = Wk rows e, B = Wq rows d,
// both native k-major. 8 warps 2(M) x 4(N); warp tile 64x32.
#define BK 64
#define STG2 32768          // 256 rows * 128 B
#define NST 4

__global__ __launch_bounds__(256, 1)
void k2_mt_gemm() {
    extern __shared__ __align__(1024) char smem[];
    const uint32_t base = smem_u32(smem);
    const int tid = threadIdx.x, warp = tid >> 5, lane = tid & 31;
    const int dBase = blockIdx.x * 128;
    const int eBase = blockIdx.y * 128;
    const int mw = (warp & 1) * 64;
    const int nw = (warp >> 1) * 32;
    const int lj = lane >> 3, li = lane & 7;

    float c[4][4][4];
    #pragma unroll
    for (int i = 0; i < 4; i++)
        #pragma unroll
        for (int j = 0; j < 4; j++)
            #pragma unroll
            for (int r = 0; r < 4; r++) c[i][j][r] = 0.f;

    const __nv_bfloat16* __restrict__ Wk_ = g_Wbf + 1048576;
    const __nv_bfloat16* __restrict__ Wq_ = g_Wbf;

    auto issue = [&](int kb) {
        const int stage = kb & (NST - 1);
        const uint32_t sA = base + (uint32_t)stage * STG2;
        const uint32_t sB = sA + 16384;
        const int k0 = kb * BK;
        #pragma unroll
        for (int i = 0; i < 4; i++) {
            const int idx = i * 256 + tid;
            const int row = idx >> 3, ch = idx & 7;
            const uint32_t swz = (uint32_t)((ch ^ (row & 7)) << 4);
            const __nv_bfloat16* gA = Wk_ + (size_t)(eBase + row) * 1024 + k0 + ch * 8;
            const __nv_bfloat16* gB = Wq_ + (size_t)(dBase + row) * 1024 + k0 + ch * 8;
            asm volatile("cp.async.cg.shared.global [%0], [%1], 16;"
                         :: "r"(sA + (uint32_t)row * 128 + swz), "l"(gA));
            asm volatile("cp.async.cg.shared.global [%0], [%1], 16;"
                         :: "r"(sB + (uint32_t)row * 128 + swz), "l"(gB));
        }
        asm volatile("cp.async.commit_group;");
    };

    auto compute = [&](int stage) {
        const uint32_t sA = base + (uint32_t)stage * STG2;
        const uint32_t sB = sA + 16384;
        #pragma unroll
        for (int kc = 0; kc < 4; kc++) {
            uint32_t a[4][4];
            #pragma unroll
            for (int mt = 0; mt < 4; mt++) {
                const int row = mw + mt * 16 + ((lj & 1) << 3) + li;
                const int ch = kc * 2 + (lj >> 1);
                asm volatile("ldmatrix.sync.aligned.m8n8.x4.shared.b16 "
                             "{%0,%1,%2,%3}, [%4];"
                             : "=r"(a[mt][0]), "=r"(a[mt][1]),
                               "=r"(a[mt][2]), "=r"(a[mt][3])
                             : "r"(sA + (uint32_t)(row * 128 + ((ch ^ (row & 7)) << 4))));
            }
            uint32_t b[2][4];
            #pragma unroll
            for (int nh = 0; nh < 2; nh++) {
                const int row = nw + nh * 16 + ((lj >> 1) << 3) + li;
                const int ch = kc * 2 + (lj & 1);
                asm volatile("ldmatrix.sync.aligned.m8n8.x4.shared.b16 "
                             "{%0,%1,%2,%3}, [%4];"
                             : "=r"(b[nh][0]), "=r"(b[nh][1]),
                               "=r"(b[nh][2]), "=r"(b[nh][3])
                             : "r"(sB + (uint32_t)(row * 128 + ((ch ^ (row & 7)) << 4))));
            }
            #pragma unroll
            for (int mt = 0; mt < 4; mt++)
                #pragma unroll
                for (int nt = 0; nt < 4; nt++) {
                    asm volatile(
                        "mma.sync.aligned.m16n8k16.row.col.f32.bf16.bf16.f32 "
                        "{%0,%1,%2,%3}, {%4,%5,%6,%7}, {%8,%9}, {%0,%1,%2,%3};"
                        : "+f"(c[mt][nt][0]), "+f"(c[mt][nt][1]),
                          "+f"(c[mt][nt][2]), "+f"(c[mt][nt][3])
                        : "r"(a[mt][0]), "r"(a[mt][1]), "r"(a[mt][2]), "r"(a[mt][3]),
                          "r"(b[nt >> 1][(nt & 1) * 2]),
                          "r"(b[nt >> 1][(nt & 1) * 2 + 1]));
                }
        }
    };

    issue(0); issue(1); issue(2);
    for (int kb = 0; kb < 16; kb++) {
        if (kb < 14)       asm volatile("cp.async.wait_group 2;");
        else if (kb == 14) asm volatile("cp.async.wait_group 1;");
        else               asm volatile("cp.async.wait_group 0;");
        __syncthreads();
        if (kb + 3 < 16) issue(kb + 3);
        compute(kb & (NST - 1));
    }

    #pragma unroll
    for (int mt = 0; mt < 4; mt++)
        #pragma unroll
        for (int half = 0; half < 2; half++) {
            const int e = eBase + mw + mt * 16 + (lane >> 2) + half * 8;
            #pragma unroll
            for (int nt = 0; nt < 4; nt++) {
                const int d = dBase + nw + nt * 8 + (lane & 3) * 2;
                __nv_bfloat162 hv;
                hv.x = __float2bfloat16(c[mt][nt][half * 2 + 0]);
                hv.y = __float2bfloat16(c[mt][nt][half * 2 + 1]);
                *reinterpret_cast<__nv_bfloat162*>(&g_MT[(size_t)e * 1024 + d]) = hv;
            }
        }
}

// ================= K3: fused P = cls@M, S-MMA, softmax =================
// grid (8 slices, 16 pairs). CTA: 64 cls rows (2 batches) x 128 e-slice.
#define STG3 24576
#define K3_SMEM (4 * STG3 + 16384)

__global__ __launch_bounds__(256, 1)
void k3_fused(const int* __restrict__ mask, float* __restrict__ out) {
    extern __shared__ __align__(1024) char smem[];
    const uint32_t base = smem_u32(smem);
    const int tid = threadIdx.x, warp = tid >> 5, lane = tid & 31;
    const int slice = blockIdx.x;
    const int p = blockIdx.y;
    const int n0e = slice * 128;
    const int mw = (warp & 1) * 32;
    const int nw = (warp >> 1) * 32;
    const int lj = lane >> 3, li = lane & 7;
    const uint32_t clsB = base + 4 * STG3;

    #pragma unroll
    for (int i = 0; i < 4; i++) {
        const int idx = i * 256 + tid;
        const int row = idx >> 4, ch = idx & 15;
        const int swz = (ch & 8) | ((ch ^ (row & 7)) & 7);
        const __nv_bfloat16* g = g_A + (size_t)(p * 64 + row) * 1024 + n0e + ch * 8;
        asm volatile("cp.async.cg.shared.global [%0], [%1], 16;"
                     :: "r"(clsB + (uint32_t)(row * 256 + swz * 16)), "l"(g));
    }
    asm volatile("cp.async.commit_group;");

    float c[2][4][4];
    #pragma unroll
    for (int i = 0; i < 2; i++)
        #pragma unroll
        for (int j = 0; j < 4; j++)
            #pragma unroll
            for (int r = 0; r < 4; r++) c[i][j][r] = 0.f;

    auto issue = [&](int kb) {
        const int stage = kb & (NST - 1);
        const uint32_t sA = base + (uint32_t)stage * STG3;
        const uint32_t sB = sA + 8192;
        const int k0 = kb * BK;
        #pragma unroll
        for (int i = 0; i < 2; i++) {
            const int idx = i * 256 + tid;
            const int row = idx >> 3, ch = idx & 7;
            const __nv_bfloat16* g = g_A + (size_t)(p * 64 + row) * 1024 + k0 + ch * 8;
            asm volatile("cp.async.cg.shared.global [%0], [%1], 16;"
                :: "r"(sA + (uint32_t)(row * 128 + ((ch ^ (row & 7)) << 4))), "l"(g));
        }
        #pragma unroll
        for (int i = 0; i < 4; i++) {
            const int idx = i * 256 + tid;
            const int row = idx >> 3, ch = idx & 7;
            const __nv_bfloat16* g = g_MT + (size_t)(n0e + row) * 1024 + k0 + ch * 8;
            asm volatile("cp.async.cg.shared.global [%0], [%1], 16;"
                :: "r"(sB + (uint32_t)(row * 128 + ((ch ^ (row & 7)) << 4))), "l"(g));
        }
        asm volatile("cp.async.commit_group;");
    };

    auto compute = [&](int stage) {
        const uint32_t sA = base + (uint32_t)stage * STG3;
        const uint32_t sB = sA + 8192;
        #pragma unroll
        for (int kc = 0; kc < 4; kc++) {
            uint32_t a[2][4];
            #pragma unroll
            for (int mt = 0; mt < 2; mt++) {
                const int row = mw + mt * 16 + ((lj & 1) << 3) + li;
                const int ch = kc * 2 + (lj >> 1);
                asm volatile("ldmatrix.sync.aligned.m8n8.x4.shared.b16 "
                             "{%0,%1,%2,%3}, [%4];"
                             : "=r"(a[mt][0]), "=r"(a[mt][1]),
                               "=r"(a[mt][2]), "=r"(a[mt][3])
                             : "r"(sA + (uint32_t)(row * 128 + ((ch ^ (row & 7)) << 4))));
            }
            uint32_t b[2][4];
            #pragma unroll
            for (int nh = 0; nh < 2; nh++) {
                const int row = nw + nh * 16 + ((lj >> 1) << 3) + li;
                const int ch = kc * 2 + (lj & 1);
                asm volatile("ldmatrix.sync.aligned.m8n8.x4.shared.b16 "
                             "{%0,%1,%2,%3}, [%4];"
                             : "=r"(b[nh][0]), "=r"(b[nh][1]),
                               "=r"(b[nh][2]), "=r"(b[nh][3])
                             : "r"(sB + (uint32_t)(row * 128 + ((ch ^ (row & 7)) << 4))));
            }
            #pragma unroll
            for (int mt = 0; mt < 2; mt++)
                #pragma unroll
                for (int nt = 0; nt < 4; nt++) {
                    asm volatile(
                        "mma.sync.aligned.m16n8k16.row.col.f32.bf16.bf16.f32 "
                        "{%0,%1,%2,%3}, {%4,%5,%6,%7}, {%8,%9}, {%0,%1,%2,%3};"
                        : "+f"(c[mt][nt][0]), "+f"(c[mt][nt][1]),
                          "+f"(c[mt][nt][2]), "+f"(c[mt][nt][3])
                        : "r"(a[mt][0]), "r"(a[mt][1]), "r"(a[mt][2]), "r"(a[mt][3]),
                          "r"(b[nt >> 1][(nt & 1) * 2]), "r"(b[nt >> 1][(nt & 1) * 2 + 1]));
                }
        }
    };

    issue(0); issue(1); issue(2);
    for (int kb = 0; kb < 16; kb++) {
        if (kb < 14)       asm volatile("cp.async.wait_group 2;");
        else if (kb == 14) asm volatile("cp.async.wait_group 1;");
        else               asm volatile("cp.async.wait_group 0;");
        __syncthreads();
        if (kb + 3 < 16) issue(kb + 3);
        compute(kb & (NST - 1));
    }
    __syncthreads();

    #pragma unroll
    for (int mt = 0; mt < 2; mt++)
        #pragma unroll
        for (int half = 0; half < 2; half++) {
            const int x = mw + mt * 16 + (lane >> 2) + half * 8;
            #pragma unroll
            for (int nt = 0; nt < 4; nt++) {
                const int eloc = nw + nt * 8 + (lane & 3) * 2;
                const int ch = eloc >> 3;
                const int swz = (ch & 8) | ((ch ^ (x & 7)) & 7);
                __nv_bfloat162 hv;
                hv.x = __float2bfloat16(c[mt][nt][half * 2 + 0]);
                hv.y = __float2bfloat16(c[mt][nt][half * 2 + 1]);
                *reinterpret_cast<__nv_bfloat162*>(
                    smem + x * 256 + swz * 16 + (lane & 3) * 4) = hv;
            }
        }
    __syncthreads();

    float cs[2][2][4][4];
    #pragma unroll
    for (int bi = 0; bi < 2; bi++)
        #pragma unroll
        for (int i = 0; i < 2; i++)
            #pragma unroll
            for (int j = 0; j < 4; j++)
                #pragma unroll
                for (int r = 0; r < 4; r++) cs[bi][i][j][r] = 0.f;
    {
        uint32_t as[4][4], bs[4][4];
        #pragma unroll
        for (int mt = 0; mt < 4; mt++) {
            const int row = mt * 16 + ((lj & 1) << 3) + li;
            const int ch = warp * 2 + (lj >> 1);
            const int swz = (ch & 8) | ((ch ^ (row & 7)) & 7);
            asm volatile("ldmatrix.sync.aligned.m8n8.x4.shared.b16 "
                         "{%0,%1,%2,%3}, [%4];"
                         : "=r"(as[mt][0]), "=r"(as[mt][1]),
                           "=r"(as[mt][2]), "=r"(as[mt][3])
                         : "r"(base + (uint32_t)(row * 256 + swz * 16)));
        }
        #pragma unroll
        for (int nh = 0; nh < 4; nh++) {
            const int row = nh * 16 + ((lj >> 1) << 3) + li;
            const int ch = warp * 2 + (lj & 1);
            const int swz = (ch & 8) | ((ch ^ (row & 7)) & 7);
            asm volatile("ldmatrix.sync.aligned.m8n8.x4.shared.b16 "
                         "{%0,%1,%2,%3}, [%4];"
                         : "=r"(bs[nh][0]), "=r"(bs[nh][1]),
                           "=r"(bs[nh][2]), "=r"(bs[nh][3])
                         : "r"(clsB + (uint32_t)(row * 256 + swz * 16)));
        }
        #pragma unroll
        for (int bi = 0; bi < 2; bi++)
            #pragma unroll
            for (int mtl = 0; mtl < 2; mtl++) {
                const int mt = bi * 2 + mtl;
                #pragma unroll
                for (int ntl = 0; ntl < 4; ntl++) {
                    const int ng = bi * 4 + ntl;
                    asm volatile(
                        "mma.sync.aligned.m16n8k16.row.col.f32.bf16.bf16.f32 "
                        "{%0,%1,%2,%3}, {%4,%5,%6,%7}, {%8,%9}, {%0,%1,%2,%3};"
                        : "+f"(cs[bi][mtl][ntl][0]), "+f"(cs[bi][mtl][ntl][1]),
                          "+f"(cs[bi][mtl][ntl][2]), "+f"(cs[bi][mtl][ntl][3])
                        : "r"(as[mt][0]), "r"(as[mt][1]), "r"(as[mt][2]), "r"(as[mt][3]),
                          "r"(bs[ng >> 1][(ng & 1) * 2]), "r"(bs[ng >> 1][(ng & 1) * 2 + 1]));
                }
            }
    }
    float* __restrict__ S8 = reinterpret_cast<float*>(smem + 16384);
    #pragma unroll
    for (int bi = 0; bi < 2; bi++)
        #pragma unroll
        for (int mtl = 0; mtl < 2; mtl++)
            #pragma unroll
            for (int half = 0; half < 2; half++) {
                const int xl = mtl * 16 + (lane >> 2) + half * 8;
                #pragma unroll
                for (int ntl = 0; ntl < 4; ntl++) {
                    const int y = ntl * 8 + (lane & 3) * 2;
                    float2 v;
                    v.x = cs[bi][mtl][ntl][half * 2 + 0];
                    v.y = cs[bi][mtl][ntl][half * 2 + 1];
                    *reinterpret_cast<float2*>(
                        &S8[(warp * 2 + bi) * 1024 + xl * 32 + y]) = v;
                }
            }
    __syncthreads();

    #pragma unroll
    for (int t = 0; t < 8; t++) {
        const int idx = tid + t * 256;
        const int bi = idx >> 10, e = idx & 1023;
        float s = 0.f;
        #pragma unroll
        for (int w8 = 0; w8 < 8; w8++) s += S8[(w8 * 2 + bi) * 1024 + e];
        g_part[(size_t)(p * 2 + bi) * 8192 + slice * 1024 + e] = s;
    }

    __shared__ int lastF[2];
    __syncthreads();
    if (tid == 0) {
        __threadfence();
        lastF[0] = (atomicAdd(&g_bctr[p * 2 + 0], 1) == 7);
        lastF[1] = (atomicAdd(&g_bctr[p * 2 + 1], 1) == 7);
    }
    __syncthreads();

    __shared__ float Sf[1024];
    __shared__ float mrow[32], tv[32], rv[32], lg[32], scal[2];
    #pragma unroll
    for (int bi = 0; bi < 2; bi++) {
        if (!lastF[bi]) continue;
        const int b = p * 2 + bi;
        if (tid == 0) __threadfence();
        __syncthreads();
        #pragma unroll
        for (int t = 0; t < 4; t++) {
            const int idx = tid + t * 256;
            float s = 0.f;
            #pragma unroll
            for (int sl = 0; sl < 8; sl++)
                s += g_part[(size_t)b * 8192 + sl * 1024 + idx];
            Sf[idx] = s;
        }
        if (tid < 32) mrow[tid] = (float)mask[b * 32 + tid];
        __syncthreads();
        #pragma unroll
        for (int xi = 0; xi < 4; xi++) {
            const int x = warp * 4 + xi;
            const __nv_bfloat16* __restrict__ crow = g_A + (size_t)(b * 32 + x) * 1024;
            float ta = 0.f, ra = 0.f;
            #pragma unroll
            for (int j = 0; j < 32; j++) {
                const int d = lane + j * 32;
                const float cv = __bfloat162float(crow[d]);
                ta = fmaf(cv, g_u[d], ta);
                ra = fmaf(cv, g_v[d], ra);
            }
            #pragma unroll
            for (int o = 16; o > 0; o >>= 1) {
                ta += __shfl_xor_sync(0xFFFFFFFFu, ta, o);
                ra += __shfl_xor_sync(0xFFFFFFFFu, ra, o);
            }
            if (lane == 0) { tv[x] = ta; rv[x] = ra; }
        }
        __syncthreads();
        if (warp == 0) {
            float R = mrow[lane] * rv[lane];
            float cA = mrow[lane];
            #pragma unroll
            for (int o = 16; o > 0; o >>= 1) {
                R += __shfl_xor_sync(0xFFFFFFFFu, R, o);
                cA += __shfl_xor_sync(0xFFFFFFFFu, cA, o);
            }
            if (lane == 0) { scal[0] = R; scal[1] = cA; }
        }
        __syncthreads();
        const float R = scal[0], cA = scal[1], c0 = g_c0;
        #pragma unroll
        for (int xi = 0; xi < 4; xi++) {
            const int x = warp * 4 + xi;
            float s = mrow[lane] * Sf[x * 32 + lane];
            #pragma unroll
            for (int o = 16; o > 0; o >>= 1)
                s += __shfl_xor_sync(0xFFFFFFFFu, s, o);
            if (lane == 0)
                lg[x] = (mrow[x] != 0.f)
                    ? (s - Sf[x * 33] + tv[x] * (cA - 1.f) + (R - rv[x]) + c0 * (cA - 1.f))
                    : -100000.0f;
        }
        __syncthreads();
        if (warp == 0) {
            float v = lg[lane];
            float mx = v;
            #pragma unroll
            for (int o = 16; o > 0; o >>= 1)
                mx = fmaxf(mx, __shfl_xor_sync(0xFFFFFFFFu, mx, o));
            const float e = expf(v - mx);
            float sum = e;
            #pragma unroll
            for (int o = 16; o > 0; o >>= 1)
                sum += __shfl_xor_sync(0xFFFFFFFFu, sum, o);
            out[b * 32 + lane] = e / sum;
        }
        if (tid == 0) g_bctr[b] = 0;
        __syncthreads();
    }
}

extern "C" void kernel_launch(void* const* d_in, const int* in_sizes, int n_in,
                              void* d_out, int out_size) {
    const float* enc  = (const float*)d_in[0];
    const int*   mask = (const int*)  d_in[1];
    const float* wq   = (const float*)d_in[2];
    const float* bq   = (const float*)d_in[3];
    const float* wk   = (const float*)d_in[4];
    const float* bk   = (const float*)d_in[5];
    float* out = (float*)d_out;

    cudaFuncSetAttribute(k2_mt_gemm, cudaFuncAttributeMaxDynamicSharedMemorySize,
                         NST * STG2);
    cudaFuncSetAttribute(k3_fused, cudaFuncAttributeMaxDynamicSharedMemorySize,
                         K3_SMEM);

    k1_convert<<<385, 256>>>(enc, wq, wk, bq, bk);
    k2_mt_gemm<<<dim3(8, 8), 256, NST * STG2>>>();
    k3_fused<<<dim3(8, 16), 256, K3_SMEM>>>(mask, out);
}